// round 14
// baseline (speedup 1.0000x reference)
#include <cuda_runtime.h>

#define BT 32
#define TPB 832     // 26 warps: 13 layer-1+partial (A) + 13 layer-2 (B)
#define L2E 1.4426950408889634f

// Transposed x: xT[t][b]. 8 MB static device buffer.
__device__ float g_xT[512 * 4096];

__global__ void transpose_kernel(const float* __restrict__ x, int B, int T) {
    __shared__ float tile[32][33];
    int bx = blockIdx.x * 32;  // t offset
    int by = blockIdx.y * 32;  // b offset
    int tx = threadIdx.x, ty = threadIdx.y;
#pragma unroll
    for (int i = 0; i < 32; i += 8)
        tile[ty + i][tx] = x[(size_t)(by + ty + i) * T + (bx + tx)];
    __syncthreads();
#pragma unroll
    for (int i = 0; i < 32; i += 8)
        g_xT[(size_t)(bx + ty + i) * B + (by + tx)] = tile[tx][ty + i];
}

// -------------------- f32x2 helpers (sm_103a FFMA2) --------------------
typedef unsigned long long ull;
__device__ __forceinline__ ull pack2(float a, float b) {
    ull r;
    asm("mov.b64 %0, {%1, %2};" : "=l"(r)
        : "r"(__float_as_uint(a)), "r"(__float_as_uint(b)));
    return r;
}
__device__ __forceinline__ float2 unpack2(ull v) {
    unsigned lo, hi;
    asm("mov.b64 {%0, %1}, %2;" : "=r"(lo), "=r"(hi) : "l"(v));
    return make_float2(__uint_as_float(lo), __uint_as_float(hi));
}
__device__ __forceinline__ void ffma2(ull& d, ull a, ull b) {
    asm("fma.rn.f32x2 %0, %1, %2, %0;" : "+l"(d) : "l"(a), "l"(b));
}
__device__ __forceinline__ float ex2f(float x) {   // 2^x, 1 MUFU
    float r; asm("ex2.approx.ftz.f32 %0, %1;" : "=f"(r) : "f"(x)); return r;
}
__device__ __forceinline__ float rcpf(float x) {   // 1/x, 1 MUFU
    float r; asm("rcp.approx.ftz.f32 %0, %1;" : "=f"(r) : "f"(x)); return r;
}

// Gate inputs arrive PRE-SCALED: i,f,o by log2e; g by 2*log2e (folded into weights).
// Returns new c and h via merged-RCP form (7 MUFU total).
__device__ __forceinline__ void lstm_cell(float gi, float gf, float gg, float go,
                                          float& c, float& h) {
    float F  = ex2f(-gf);
    float Ai = ex2f(-gi);
    float Bv = ex2f(-gg);
    float O  = ex2f(-go);
    float pF = 1.f + F, pA = 1.f + Ai, pB = 1.f + Bv;
    float X  = pA * pB;
    float num = fmaf(c, X, (1.f - Bv) * pF);
    float cn  = num * rcpf(X * pF);
    c = cn;
    float C2 = ex2f(-2.f * L2E * cn);
    float r2 = rcpf((1.f + O) * (1.f + C2));
    h = (1.f - C2) * r2;
}

// smem layout (floats):
//  W1n: 13kg*13j*4g*16 = 10816 @ 0          (scaled by gate: i,f,o x L2E; g x 2*L2E)
//  W2n: 13kg*26j*4g*16 = 21632 @ 10816      kp m=j*4+c: m<50 -> W_ih1; 52<=m<102 -> W_hh1[m-52]
//  wx1n/bs1n/bs2n: 208 each @ 32448/32656/32864  (same gate scaling)
//  hcT: 32 b * 156 = 4992 @ 33072. Per b: [0..51] h1 buf0, [52..103] h1 buf1, [104..155] h2
//  pbuf: 2 bufs * 1696 float4 (stride 53/row, conflict-free) = 13568 @ 38064
#define SME_TOT 51632

__global__ __launch_bounds__(TPB, 1) void lstm_kernel(
    const float* __restrict__ W_ih0, const float* __restrict__ W_hh0,
    const float* __restrict__ b_ih0, const float* __restrict__ b_hh0,
    const float* __restrict__ W_ih1, const float* __restrict__ W_hh1,
    const float* __restrict__ b_ih1, const float* __restrict__ b_hh1,
    const float* __restrict__ W_fc, const float* __restrict__ b_fc,
    float* __restrict__ out, int B, int T)
{
    extern __shared__ float sm[];
    float* W1n  = sm;
    float* W2n  = sm + 10816;
    float* wx1n = sm + 32448;
    float* bs1n = sm + 32656;
    float* bs2n = sm + 32864;
    float* hcT  = sm + 33072;
    float* pbuf = sm + 38064;
    float4* pbuf4 = (float4*)pbuf;   // 1696 float4 per parity buffer (row stride 53)

    const int tid = threadIdx.x;

    // ---- pack weights (with log2e gate-fold: i,f,o x L2E; g x 2*L2E) ----
    for (int i = tid; i < 10816; i += TPB) {
        int kg = i / 832, r = i % 832;
        int j = r / 64, g = (r % 64) / 16, k_id = (r % 16) / 4, c = i & 3;
        int k = kg * 4 + k_id, kp = j * 4 + c;
        float sc = (g == 2) ? 2.f * L2E : L2E;
        W1n[i] = (k < 50 && kp < 50) ? W_hh0[(g * 50 + k) * 50 + kp] * sc : 0.f;
    }
    for (int i = tid; i < 21632; i += TPB) {
        int kg = i / 1664, r = i % 1664;
        int j = r / 64, g = (r % 64) / 16, k_id = (r % 16) / 4, c = i & 3;
        int k = kg * 4 + k_id, m = j * 4 + c;
        float sc = (g == 2) ? 2.f * L2E : L2E;
        float v = 0.f;
        if (k < 50) {
            if (m < 50)                  v = W_ih1[(g * 50 + k) * 50 + m] * sc;
            else if (m >= 52 && m < 102) v = W_hh1[(g * 50 + k) * 50 + (m - 52)] * sc;
        }
        W2n[i] = v;
    }
    for (int i = tid; i < 208; i += TPB) {
        int kg = i / 16, k_id = (i % 16) / 4, g = i & 3;
        int k = kg * 4 + k_id;
        float sc = (g == 2) ? 2.f * L2E : L2E;
        wx1n[i] = (k < 50) ? W_ih0[g * 50 + k] * sc : 0.f;
        bs1n[i] = (k < 50) ? (b_ih0[g * 50 + k] + b_hh0[g * 50 + k]) * sc : 0.f;
        bs2n[i] = (k < 50) ? (b_ih1[g * 50 + k] + b_hh1[g * 50 + k]) * sc : 0.f;
    }
    for (int i = tid; i < 4992; i += TPB) hcT[i] = 0.f;
    for (int i = tid; i < 13568; i += TPB) pbuf[i] = 0.f;

    const int wid  = tid >> 5;
    const bool isA = (wid < 13);
    const int kg   = isA ? wid : wid - 13;
    const int lane = tid & 31;
    const int k_id = lane & 3;
    const int b_id = lane >> 2;       // 0..7; batch b = bg*8 + b_id, bg 0..3
    const int k    = kg * 4 + k_id;
    const bool kvalid = (k < 50);
    const int bbase = blockIdx.x * BT;

    // h base (ull2): 156 floats per b = 39 ull2; bg stride = 8*39 = 312
    const ulonglong2* hb = (const ulonglong2*)hcT + b_id * 39;

    __syncthreads();

    if (isA) {
        // ===== A warps: layer-1 h1(s) + L2 h1-part partial (j2=0..5) for h2(s-1) =====
        const ulonglong2* W1p = (const ulonglong2*)W1n + kg * 208 + k_id;
        const ulonglong2* W2p = (const ulonglong2*)W2n + kg * 416 + k_id;
        const float4 wx4 = *(const float4*)(wx1n + (kg * 4 + k_id) * 4);
        const float4 b14 = *(const float4*)(bs1n + (kg * 4 + k_id) * 4);
        float c1[4] = {0.f, 0.f, 0.f, 0.f};
        float nh[4];

        for (int s = 0; s <= T; s++) {
            const int rd = ((s & 1) ^ 1) * 13;   // h1(s-1) buf (ull2 offset)

            if (s < T) {
                const float* xrow = g_xT + (size_t)s * B + bbase + b_id;
                float xv0 = xrow[0], xv1 = xrow[8], xv2 = xrow[16], xv3 = xrow[24];

                ull a[4][4];
#pragma unroll
                for (int bg = 0; bg < 4; bg++) {
                    a[bg][0] = pack2(b14.x, 0.f); a[bg][1] = pack2(b14.y, 0.f);
                    a[bg][2] = pack2(b14.z, 0.f); a[bg][3] = pack2(b14.w, 0.f);
                }
#pragma unroll
                for (int j = 0; j < 13; j++) {
                    ulonglong2 w0 = W1p[(j * 4 + 0) * 4];
                    ulonglong2 w1 = W1p[(j * 4 + 1) * 4];
                    ulonglong2 w2 = W1p[(j * 4 + 2) * 4];
                    ulonglong2 w3 = W1p[(j * 4 + 3) * 4];
#pragma unroll
                    for (int bg = 0; bg < 4; bg++) {
                        ulonglong2 h = hb[bg * 312 + rd + j];
                        ffma2(a[bg][0], w0.x, h.x); ffma2(a[bg][0], w0.y, h.y);
                        ffma2(a[bg][1], w1.x, h.x); ffma2(a[bg][1], w1.y, h.y);
                        ffma2(a[bg][2], w2.x, h.x); ffma2(a[bg][2], w2.y, h.y);
                        ffma2(a[bg][3], w3.x, h.x); ffma2(a[bg][3], w3.y, h.y);
                    }
                }
                float xv[4] = {xv0, xv1, xv2, xv3};
#pragma unroll
                for (int bg = 0; bg < 4; bg++) {
                    float2 vi = unpack2(a[bg][0]), vf = unpack2(a[bg][1]);
                    float2 vg = unpack2(a[bg][2]), vo = unpack2(a[bg][3]);
                    float gi = fmaf(xv[bg], wx4.x, vi.x + vi.y);
                    float gf = fmaf(xv[bg], wx4.y, vf.x + vf.y);
                    float gg = fmaf(xv[bg], wx4.z, vg.x + vg.y);
                    float go = fmaf(xv[bg], wx4.w, vo.x + vo.y);
                    lstm_cell(gi, gf, gg, go, c1[bg], nh[bg]);
                }
                if (kvalid) {
                    const int wr = (s & 1) * 52;
#pragma unroll
                    for (int bg = 0; bg < 4; bg++)
                        hcT[(bg * 8 + b_id) * 156 + wr + k] = nh[bg];
                }
            }

            // ---- L2 h1-part partial over kp chunks j2=0..5 of h1(s-1) -> pbuf[s&1] ----
            if (s >= 1) {
                ull p[4][4];
#pragma unroll
                for (int bg = 0; bg < 4; bg++) {
                    p[bg][0] = pack2(0.f, 0.f); p[bg][1] = pack2(0.f, 0.f);
                    p[bg][2] = pack2(0.f, 0.f); p[bg][3] = pack2(0.f, 0.f);
                }
#pragma unroll
                for (int j = 0; j < 6; j++) {
                    ulonglong2 w0 = W2p[(j * 4 + 0) * 4];
                    ulonglong2 w1 = W2p[(j * 4 + 1) * 4];
                    ulonglong2 w2 = W2p[(j * 4 + 2) * 4];
                    ulonglong2 w3 = W2p[(j * 4 + 3) * 4];
#pragma unroll
                    for (int bg = 0; bg < 4; bg++) {
                        ulonglong2 h = hb[bg * 312 + rd + j];
                        ffma2(p[bg][0], w0.x, h.x); ffma2(p[bg][0], w0.y, h.y);
                        ffma2(p[bg][1], w1.x, h.x); ffma2(p[bg][1], w1.y, h.y);
                        ffma2(p[bg][2], w2.x, h.x); ffma2(p[bg][2], w2.y, h.y);
                        ffma2(p[bg][3], w3.x, h.x); ffma2(p[bg][3], w3.y, h.y);
                    }
                }
                if (kvalid) {
                    const int pb = (s & 1) * 1696;
#pragma unroll
                    for (int bg = 0; bg < 4; bg++) {
                        float2 q0 = unpack2(p[bg][0]), q1 = unpack2(p[bg][1]);
                        float2 q2 = unpack2(p[bg][2]), q3 = unpack2(p[bg][3]);
                        float4 P;
                        P.x = q0.x + q0.y; P.y = q1.x + q1.y;
                        P.z = q2.x + q2.y; P.w = q3.x + q3.y;
                        pbuf4[pb + (bg * 8 + b_id) * 53 + k] = P;
                    }
                }
            }
            // single joint barrier per superstep: publishes h1(s) + pbuf(s),
            // and back-pressures pbuf parity reuse.
            asm volatile("bar.sync 2, 832;" ::: "memory");
        }
    } else {
        // ===== B warps: L2 h1-part (j2=6..12) + h2-part; h2(s-1) at superstep s =====
        const ulonglong2* W2p = (const ulonglong2*)W2n + kg * 416 + k_id;
        const float4 b24 = *(const float4*)(bs2n + (kg * 4 + k_id) * 4);
        float c2[4] = {0.f, 0.f, 0.f, 0.f};
        float nh[4];

        for (int s = 0; s <= T; s++) {
            // B-only barrier: h2 writes of superstep s-1 done before reads below
            asm volatile("bar.sync 1, 416;" ::: "memory");

            ull a[4][4];
            if (s >= 1) {
                const int rd = ((s & 1) ^ 1) * 13;   // h1(s-1) buf
#pragma unroll
                for (int bg = 0; bg < 4; bg++) {
                    a[bg][0] = pack2(b24.x, 0.f); a[bg][1] = pack2(b24.y, 0.f);
                    a[bg][2] = pack2(b24.z, 0.f); a[bg][3] = pack2(b24.w, 0.f);
                }
                // h1-section chunks j2 = 6..12
#pragma unroll
                for (int j = 6; j < 13; j++) {
                    ulonglong2 w0 = W2p[(j * 4 + 0) * 4];
                    ulonglong2 w1 = W2p[(j * 4 + 1) * 4];
                    ulonglong2 w2 = W2p[(j * 4 + 2) * 4];
                    ulonglong2 w3 = W2p[(j * 4 + 3) * 4];
#pragma unroll
                    for (int bg = 0; bg < 4; bg++) {
                        ulonglong2 h = hb[bg * 312 + rd + j];
                        ffma2(a[bg][0], w0.x, h.x); ffma2(a[bg][0], w0.y, h.y);
                        ffma2(a[bg][1], w1.x, h.x); ffma2(a[bg][1], w1.y, h.y);
                        ffma2(a[bg][2], w2.x, h.x); ffma2(a[bg][2], w2.y, h.y);
                        ffma2(a[bg][3], w3.x, h.x); ffma2(a[bg][3], w3.y, h.y);
                    }
                }
                // h2-section chunks (region offset 26 ull2)
#pragma unroll
                for (int jh = 0; jh < 13; jh++) {
                    ulonglong2 w0 = W2p[((13 + jh) * 4 + 0) * 4];
                    ulonglong2 w1 = W2p[((13 + jh) * 4 + 1) * 4];
                    ulonglong2 w2 = W2p[((13 + jh) * 4 + 2) * 4];
                    ulonglong2 w3 = W2p[((13 + jh) * 4 + 3) * 4];
#pragma unroll
                    for (int bg = 0; bg < 4; bg++) {
                        ulonglong2 h = hb[bg * 312 + 26 + jh];
                        ffma2(a[bg][0], w0.x, h.x); ffma2(a[bg][0], w0.y, h.y);
                        ffma2(a[bg][1], w1.x, h.x); ffma2(a[bg][1], w1.y, h.y);
                        ffma2(a[bg][2], w2.x, h.x); ffma2(a[bg][2], w2.y, h.y);
                        ffma2(a[bg][3], w3.x, h.x); ffma2(a[bg][3], w3.y, h.y);
                    }
                }
            }
            // joint barrier: A's pbuf(s) + h1(s) ready
            asm volatile("bar.sync 2, 832;" ::: "memory");
            if (s >= 1) {
                const int pb = (s & 1) * 1696;
#pragma unroll
                for (int bg = 0; bg < 4; bg++) {
                    float4 P = pbuf4[pb + (bg * 8 + b_id) * 53 + k];
                    float2 vi = unpack2(a[bg][0]), vf = unpack2(a[bg][1]);
                    float2 vg = unpack2(a[bg][2]), vo = unpack2(a[bg][3]);
                    lstm_cell(vi.x + vi.y + P.x, vf.x + vf.y + P.y,
                              vg.x + vg.y + P.z, vo.x + vo.y + P.w,
                              c2[bg], nh[bg]);
                }
                if (kvalid) {
#pragma unroll
                    for (int bg = 0; bg < 4; bg++)
                        hcT[(bg * 8 + b_id) * 156 + 104 + k] = nh[bg];
                }
            }
        }
    }

    __syncthreads();
    // ---- final FC: h2(T-1) lives at region 104 ----
    if (tid < BT) {
        float acc = b_fc[0];
#pragma unroll 10
        for (int kk = 0; kk < 50; kk++)
            acc = fmaf(hcT[tid * 156 + 104 + kk], W_fc[kk], acc);
        out[bbase + tid] = acc;
    }
}

extern "C" void kernel_launch(void* const* d_in, const int* in_sizes, int n_in,
                              void* d_out, int out_size) {
    const float* x     = (const float*)d_in[0];
    const float* W_ih0 = (const float*)d_in[1];
    const float* W_hh0 = (const float*)d_in[2];
    const float* b_ih0 = (const float*)d_in[3];
    const float* b_hh0 = (const float*)d_in[4];
    const float* W_ih1 = (const float*)d_in[5];
    const float* W_hh1 = (const float*)d_in[6];
    const float* b_ih1 = (const float*)d_in[7];
    const float* b_hh1 = (const float*)d_in[8];
    const float* W_fc  = (const float*)d_in[9];
    const float* b_fc  = (const float*)d_in[10];
    float* out = (float*)d_out;

    int B = out_size;                 // 4096
    int T = in_sizes[0] / B;          // 512

    dim3 tb(32, 8), tg(T / 32, B / 32);
    transpose_kernel<<<tg, tb>>>(x, B, T);

    cudaFuncSetAttribute(lstm_kernel, cudaFuncAttributeMaxDynamicSharedMemorySize,
                         SME_TOT * sizeof(float));
    lstm_kernel<<<B / BT, TPB, SME_TOT * sizeof(float)>>>(
        W_ih0, W_hh0, b_ih0, b_hh0, W_ih1, W_hh1, b_ih1, b_hh1,
        W_fc, b_fc, out, B, T);
}

// round 15
// speedup vs baseline: 1.0700x; 1.0700x over previous
#include <cuda_runtime.h>

#define BT 32
#define TPB 832     // 26 warps: 13 layer-1+partial (A) + 13 layer-2 (B)
#define L2E 1.4426950408889634f

// Transposed x: xT[t][b]. 8 MB static device buffer.
__device__ float g_xT[512 * 4096];

__global__ void transpose_kernel(const float* __restrict__ x, int B, int T) {
    __shared__ float tile[32][33];
    int bx = blockIdx.x * 32;  // t offset
    int by = blockIdx.y * 32;  // b offset
    int tx = threadIdx.x, ty = threadIdx.y;
#pragma unroll
    for (int i = 0; i < 32; i += 8)
        tile[ty + i][tx] = x[(size_t)(by + ty + i) * T + (bx + tx)];
    __syncthreads();
#pragma unroll
    for (int i = 0; i < 32; i += 8)
        g_xT[(size_t)(bx + ty + i) * B + (by + tx)] = tile[tx][ty + i];
}

// -------------------- f32x2 helpers (sm_103a FFMA2) --------------------
typedef unsigned long long ull;
__device__ __forceinline__ ull pack2(float a, float b) {
    ull r;
    asm("mov.b64 %0, {%1, %2};" : "=l"(r)
        : "r"(__float_as_uint(a)), "r"(__float_as_uint(b)));
    return r;
}
__device__ __forceinline__ float2 unpack2(ull v) {
    unsigned lo, hi;
    asm("mov.b64 {%0, %1}, %2;" : "=r"(lo), "=r"(hi) : "l"(v));
    return make_float2(__uint_as_float(lo), __uint_as_float(hi));
}
__device__ __forceinline__ void ffma2(ull& d, ull a, ull b) {
    asm("fma.rn.f32x2 %0, %1, %2, %0;" : "+l"(d) : "l"(a), "l"(b));
}
__device__ __forceinline__ float ex2f(float x) {   // 2^x, 1 MUFU
    float r; asm("ex2.approx.ftz.f32 %0, %1;" : "=f"(r) : "f"(x)); return r;
}
__device__ __forceinline__ float rcpf(float x) {   // 1/x, 1 MUFU
    float r; asm("rcp.approx.ftz.f32 %0, %1;" : "=f"(r) : "f"(x)); return r;
}

// Gate inputs arrive PRE-SCALED: i,f,o by log2e; g by 2*log2e (folded into weights).
// Returns new c and h via merged-RCP form (7 MUFU total).
__device__ __forceinline__ void lstm_cell(float gi, float gf, float gg, float go,
                                          float& c, float& h) {
    float F  = ex2f(-gf);
    float Ai = ex2f(-gi);
    float Bv = ex2f(-gg);
    float O  = ex2f(-go);
    float pF = 1.f + F, pA = 1.f + Ai, pB = 1.f + Bv;
    float X  = pA * pB;
    float num = fmaf(c, X, (1.f - Bv) * pF);
    float cn  = num * rcpf(X * pF);
    c = cn;
    float C2 = ex2f(-2.f * L2E * cn);
    float r2 = rcpf((1.f + O) * (1.f + C2));
    h = (1.f - C2) * r2;
}

// smem layout (floats):
//  W1n: 13kg*13j*4g*16 = 10816 @ 0          (scaled by gate: i,f,o x L2E; g x 2*L2E)
//  W2n: 13kg*26j*4g*16 = 21632 @ 10816      kp m=j*4+c: m<50 -> W_ih1; 52<=m<102 -> W_hh1[m-52]
//  wx1n/bs1n/bs2n: 208 each @ 32448/32656/32864  (same gate scaling)
//  hcT: 32 b * 156 = 4992 @ 33072. Per b: [0..51] h1 buf0, [52..103] h1 buf1, [104..155] h2
//  pbuf: 2 bufs * 1664 float4 (row stride 52, conflict-free) = 13312 @ 38064
#define SME_TOT 51376

__global__ __launch_bounds__(TPB, 1) void lstm_kernel(
    const float* __restrict__ W_ih0, const float* __restrict__ W_hh0,
    const float* __restrict__ b_ih0, const float* __restrict__ b_hh0,
    const float* __restrict__ W_ih1, const float* __restrict__ W_hh1,
    const float* __restrict__ b_ih1, const float* __restrict__ b_hh1,
    const float* __restrict__ W_fc, const float* __restrict__ b_fc,
    float* __restrict__ out, int B, int T)
{
    extern __shared__ float sm[];
    float* W1n  = sm;
    float* W2n  = sm + 10816;
    float* wx1n = sm + 32448;
    float* bs1n = sm + 32656;
    float* bs2n = sm + 32864;
    float* hcT  = sm + 33072;
    float* pbuf = sm + 38064;
    float4* pbuf4 = (float4*)pbuf;   // 1664 float4 per parity buffer (row stride 52)

    const int tid = threadIdx.x;

    // ---- pack weights (with log2e gate-fold: i,f,o x L2E; g x 2*L2E) ----
    for (int i = tid; i < 10816; i += TPB) {
        int kg = i / 832, r = i % 832;
        int j = r / 64, g = (r % 64) / 16, k_id = (r % 16) / 4, c = i & 3;
        int k = kg * 4 + k_id, kp = j * 4 + c;
        float sc = (g == 2) ? 2.f * L2E : L2E;
        W1n[i] = (k < 50 && kp < 50) ? W_hh0[(g * 50 + k) * 50 + kp] * sc : 0.f;
    }
    for (int i = tid; i < 21632; i += TPB) {
        int kg = i / 1664, r = i % 1664;
        int j = r / 64, g = (r % 64) / 16, k_id = (r % 16) / 4, c = i & 3;
        int k = kg * 4 + k_id, m = j * 4 + c;
        float sc = (g == 2) ? 2.f * L2E : L2E;
        float v = 0.f;
        if (k < 50) {
            if (m < 50)                  v = W_ih1[(g * 50 + k) * 50 + m] * sc;
            else if (m >= 52 && m < 102) v = W_hh1[(g * 50 + k) * 50 + (m - 52)] * sc;
        }
        W2n[i] = v;
    }
    for (int i = tid; i < 208; i += TPB) {
        int kg = i / 16, k_id = (i % 16) / 4, g = i & 3;
        int k = kg * 4 + k_id;
        float sc = (g == 2) ? 2.f * L2E : L2E;
        wx1n[i] = (k < 50) ? W_ih0[g * 50 + k] * sc : 0.f;
        bs1n[i] = (k < 50) ? (b_ih0[g * 50 + k] + b_hh0[g * 50 + k]) * sc : 0.f;
        bs2n[i] = (k < 50) ? (b_ih1[g * 50 + k] + b_hh1[g * 50 + k]) * sc : 0.f;
    }
    for (int i = tid; i < 4992; i += TPB) hcT[i] = 0.f;
    for (int i = tid; i < 13312; i += TPB) pbuf[i] = 0.f;

    const int wid  = tid >> 5;
    const bool isA = (wid < 13);
    const int kg   = isA ? wid : wid - 13;
    const int lane = tid & 31;
    const int k_id = lane & 3;
    const int b_id = lane >> 2;       // 0..7; batch b = bg*8 + b_id, bg 0..3
    const int k    = kg * 4 + k_id;
    const bool kvalid = (k < 50);
    const int bbase = blockIdx.x * BT;

    // h base (ull2): 156 floats per b = 39 ull2; bg stride = 8*39 = 312
    const ulonglong2* hb = (const ulonglong2*)hcT + b_id * 39;

    __syncthreads();

    if (isA) {
        // ===== A warps: layer-1 h1(s) + L2 h1-part partial (j2=0..5) for h2(s-1) =====
        const ulonglong2* W1p = (const ulonglong2*)W1n + kg * 208 + k_id;
        const ulonglong2* W2p = (const ulonglong2*)W2n + kg * 416 + k_id;
        const float4 wx4 = *(const float4*)(wx1n + (kg * 4 + k_id) * 4);
        const float4 b14 = *(const float4*)(bs1n + (kg * 4 + k_id) * 4);
        float c1[4] = {0.f, 0.f, 0.f, 0.f};
        float nh[4];

        for (int s = 0; s <= T; s++) {
            const int rd = ((s & 1) ^ 1) * 13;   // h1(s-1) buf (ull2 offset)

            if (s < T) {
                const float* xrow = g_xT + (size_t)s * B + bbase + b_id;
                float xv0 = xrow[0], xv1 = xrow[8], xv2 = xrow[16], xv3 = xrow[24];

                ull a[4][4];
#pragma unroll
                for (int bg = 0; bg < 4; bg++) {
                    a[bg][0] = pack2(b14.x, 0.f); a[bg][1] = pack2(b14.y, 0.f);
                    a[bg][2] = pack2(b14.z, 0.f); a[bg][3] = pack2(b14.w, 0.f);
                }
#pragma unroll
                for (int j = 0; j < 13; j++) {
                    ulonglong2 w0 = W1p[(j * 4 + 0) * 4];
                    ulonglong2 w1 = W1p[(j * 4 + 1) * 4];
                    ulonglong2 w2 = W1p[(j * 4 + 2) * 4];
                    ulonglong2 w3 = W1p[(j * 4 + 3) * 4];
#pragma unroll
                    for (int bg = 0; bg < 4; bg++) {
                        ulonglong2 h = hb[bg * 312 + rd + j];
                        ffma2(a[bg][0], w0.x, h.x); ffma2(a[bg][0], w0.y, h.y);
                        ffma2(a[bg][1], w1.x, h.x); ffma2(a[bg][1], w1.y, h.y);
                        ffma2(a[bg][2], w2.x, h.x); ffma2(a[bg][2], w2.y, h.y);
                        ffma2(a[bg][3], w3.x, h.x); ffma2(a[bg][3], w3.y, h.y);
                    }
                }
                float xv[4] = {xv0, xv1, xv2, xv3};
#pragma unroll
                for (int bg = 0; bg < 4; bg++) {
                    float2 vi = unpack2(a[bg][0]), vf = unpack2(a[bg][1]);
                    float2 vg = unpack2(a[bg][2]), vo = unpack2(a[bg][3]);
                    float gi = fmaf(xv[bg], wx4.x, vi.x + vi.y);
                    float gf = fmaf(xv[bg], wx4.y, vf.x + vf.y);
                    float gg = fmaf(xv[bg], wx4.z, vg.x + vg.y);
                    float go = fmaf(xv[bg], wx4.w, vo.x + vo.y);
                    lstm_cell(gi, gf, gg, go, c1[bg], nh[bg]);
                }
                if (kvalid) {
                    const int wr = (s & 1) * 52;
#pragma unroll
                    for (int bg = 0; bg < 4; bg++)
                        hcT[(bg * 8 + b_id) * 156 + wr + k] = nh[bg];
                }
            }

            // ---- L2 h1-part partial over kp chunks j2=0..5 of h1(s-1) -> pbuf[s&1] ----
            if (s >= 1) {
                ull p[4][4];
#pragma unroll
                for (int bg = 0; bg < 4; bg++) {
                    p[bg][0] = pack2(0.f, 0.f); p[bg][1] = pack2(0.f, 0.f);
                    p[bg][2] = pack2(0.f, 0.f); p[bg][3] = pack2(0.f, 0.f);
                }
#pragma unroll
                for (int j = 0; j < 6; j++) {
                    ulonglong2 w0 = W2p[(j * 4 + 0) * 4];
                    ulonglong2 w1 = W2p[(j * 4 + 1) * 4];
                    ulonglong2 w2 = W2p[(j * 4 + 2) * 4];
                    ulonglong2 w3 = W2p[(j * 4 + 3) * 4];
#pragma unroll
                    for (int bg = 0; bg < 4; bg++) {
                        ulonglong2 h = hb[bg * 312 + rd + j];
                        ffma2(p[bg][0], w0.x, h.x); ffma2(p[bg][0], w0.y, h.y);
                        ffma2(p[bg][1], w1.x, h.x); ffma2(p[bg][1], w1.y, h.y);
                        ffma2(p[bg][2], w2.x, h.x); ffma2(p[bg][2], w2.y, h.y);
                        ffma2(p[bg][3], w3.x, h.x); ffma2(p[bg][3], w3.y, h.y);
                    }
                }
                if (kvalid) {
                    const int pb = (s & 1) * 1664;
#pragma unroll
                    for (int bg = 0; bg < 4; bg++) {
                        float2 q0 = unpack2(p[bg][0]), q1 = unpack2(p[bg][1]);
                        float2 q2 = unpack2(p[bg][2]), q3 = unpack2(p[bg][3]);
                        float4 P;
                        P.x = q0.x + q0.y; P.y = q1.x + q1.y;
                        P.z = q2.x + q2.y; P.w = q3.x + q3.y;
                        pbuf4[pb + (bg * 8 + b_id) * 52 + k] = P;
                    }
                }
            }
            // single joint barrier per superstep: publishes h1(s) + pbuf(s),
            // and back-pressures pbuf parity reuse.
            asm volatile("bar.sync 2, 832;" ::: "memory");
        }
    } else {
        // ===== B warps: L2 h1-part (j2=6..12) + h2-part; h2(s-1) at superstep s =====
        const ulonglong2* W2p = (const ulonglong2*)W2n + kg * 416 + k_id;
        const float4 b24 = *(const float4*)(bs2n + (kg * 4 + k_id) * 4);
        float c2[4] = {0.f, 0.f, 0.f, 0.f};
        float nh[4];

        for (int s = 0; s <= T; s++) {
            // B-only barrier: h2 writes of superstep s-1 done before reads below
            asm volatile("bar.sync 1, 416;" ::: "memory");

            ull a[4][4];
            if (s >= 1) {
                const int rd = ((s & 1) ^ 1) * 13;   // h1(s-1) buf
#pragma unroll
                for (int bg = 0; bg < 4; bg++) {
                    a[bg][0] = pack2(b24.x, 0.f); a[bg][1] = pack2(b24.y, 0.f);
                    a[bg][2] = pack2(b24.z, 0.f); a[bg][3] = pack2(b24.w, 0.f);
                }
                // h1-section chunks j2 = 6..12
#pragma unroll
                for (int j = 6; j < 13; j++) {
                    ulonglong2 w0 = W2p[(j * 4 + 0) * 4];
                    ulonglong2 w1 = W2p[(j * 4 + 1) * 4];
                    ulonglong2 w2 = W2p[(j * 4 + 2) * 4];
                    ulonglong2 w3 = W2p[(j * 4 + 3) * 4];
#pragma unroll
                    for (int bg = 0; bg < 4; bg++) {
                        ulonglong2 h = hb[bg * 312 + rd + j];
                        ffma2(a[bg][0], w0.x, h.x); ffma2(a[bg][0], w0.y, h.y);
                        ffma2(a[bg][1], w1.x, h.x); ffma2(a[bg][1], w1.y, h.y);
                        ffma2(a[bg][2], w2.x, h.x); ffma2(a[bg][2], w2.y, h.y);
                        ffma2(a[bg][3], w3.x, h.x); ffma2(a[bg][3], w3.y, h.y);
                    }
                }
                // h2-section chunks (region offset 26 ull2)
#pragma unroll
                for (int jh = 0; jh < 13; jh++) {
                    ulonglong2 w0 = W2p[((13 + jh) * 4 + 0) * 4];
                    ulonglong2 w1 = W2p[((13 + jh) * 4 + 1) * 4];
                    ulonglong2 w2 = W2p[((13 + jh) * 4 + 2) * 4];
                    ulonglong2 w3 = W2p[((13 + jh) * 4 + 3) * 4];
#pragma unroll
                    for (int bg = 0; bg < 4; bg++) {
                        ulonglong2 h = hb[bg * 312 + 26 + jh];
                        ffma2(a[bg][0], w0.x, h.x); ffma2(a[bg][0], w0.y, h.y);
                        ffma2(a[bg][1], w1.x, h.x); ffma2(a[bg][1], w1.y, h.y);
                        ffma2(a[bg][2], w2.x, h.x); ffma2(a[bg][2], w2.y, h.y);
                        ffma2(a[bg][3], w3.x, h.x); ffma2(a[bg][3], w3.y, h.y);
                    }
                }
            }
            // joint barrier: A's pbuf(s) + h1(s) ready
            asm volatile("bar.sync 2, 832;" ::: "memory");
            if (s >= 1) {
                const int pb = (s & 1) * 1664;
#pragma unroll
                for (int bg = 0; bg < 4; bg++) {
                    float4 P = pbuf4[pb + (bg * 8 + b_id) * 52 + k];
                    float2 vi = unpack2(a[bg][0]), vf = unpack2(a[bg][1]);
                    float2 vg = unpack2(a[bg][2]), vo = unpack2(a[bg][3]);
                    lstm_cell(vi.x + vi.y + P.x, vf.x + vf.y + P.y,
                              vg.x + vg.y + P.z, vo.x + vo.y + P.w,
                              c2[bg], nh[bg]);
                }
                if (kvalid) {
#pragma unroll
                    for (int bg = 0; bg < 4; bg++)
                        hcT[(bg * 8 + b_id) * 156 + 104 + k] = nh[bg];
                }
            }
        }
    }

    __syncthreads();
    // ---- final FC: h2(T-1) lives at region 104 ----
    if (tid < BT) {
        float acc = b_fc[0];
#pragma unroll 10
        for (int kk = 0; kk < 50; kk++)
            acc = fmaf(hcT[tid * 156 + 104 + kk], W_fc[kk], acc);
        out[bbase + tid] = acc;
    }
}

extern "C" void kernel_launch(void* const* d_in, const int* in_sizes, int n_in,
                              void* d_out, int out_size) {
    const float* x     = (const float*)d_in[0];
    const float* W_ih0 = (const float*)d_in[1];
    const float* W_hh0 = (const float*)d_in[2];
    const float* b_ih0 = (const float*)d_in[3];
    const float* b_hh0 = (const float*)d_in[4];
    const float* W_ih1 = (const float*)d_in[5];
    const float* W_hh1 = (const float*)d_in[6];
    const float* b_ih1 = (const float*)d_in[7];
    const float* b_hh1 = (const float*)d_in[8];
    const float* W_fc  = (const float*)d_in[9];
    const float* b_fc  = (const float*)d_in[10];
    float* out = (float*)d_out;

    int B = out_size;                 // 4096
    int T = in_sizes[0] / B;          // 512

    dim3 tb(32, 8), tg(T / 32, B / 32);
    transpose_kernel<<<tg, tb>>>(x, B, T);

    cudaFuncSetAttribute(lstm_kernel, cudaFuncAttributeMaxDynamicSharedMemorySize,
                         SME_TOT * sizeof(float));
    lstm_kernel<<<B / BT, TPB, SME_TOT * sizeof(float)>>>(
        W_ih0, W_hh0, b_ih0, b_hh0, W_ih1, W_hh1, b_ih1, b_hh1,
        W_fc, b_fc, out, B, T);
}